// round 7
// baseline (speedup 1.0000x reference)
#include <cuda_runtime.h>
#include <cuda_bf16.h>
#include <math.h>
#include <stdint.h>

#define B_    2
#define S_    4096
#define D_    2048
#define H_    16
#define DK_   128
#define DV_   128
#define SEG_  512
#define NSEG_ 8
#define DH_   8192
#define M_    (B_*S_)   // 8192 rows

// ---------------- scratch (device globals; no allocation allowed) ----------------
__device__ __align__(16) float g_att[M_ * H_ * DV_];
__device__ __align__(16) float g_y  [M_ * D_];
__device__ __align__(16) float g_U  [B_*H_*NSEG_ * DK_ * DV_];
__device__ __align__(16) float g_zU [B_*H_*NSEG_ * DK_];
__device__ __align__(16) float g_mem[B_*H_*NSEG_ * DK_ * DV_];
__device__ __align__(16) float g_z  [B_*H_*NSEG_ * DK_];
// bf16 hi/lo pairs
__device__ __align__(16) __nv_bfloat16 g_xh [M_ * D_],    g_xl [M_ * D_];
__device__ __align__(16) __nv_bfloat16 g_wqh[D_ * D_],    g_wql[D_ * D_];
__device__ __align__(16) __nv_bfloat16 g_wkh[D_ * D_],    g_wkl[D_ * D_];
__device__ __align__(16) __nv_bfloat16 g_wvh[D_ * D_],    g_wvl[D_ * D_];
__device__ __align__(16) __nv_bfloat16 g_woh[D_ * D_],    g_wol[D_ * D_];
__device__ __align__(16) __nv_bfloat16 g_w1h[D_ * DH_],   g_w1l[D_ * DH_];
__device__ __align__(16) __nv_bfloat16 g_w2h[DH_ * D_],   g_w2l[DH_ * D_];
__device__ __align__(16) __nv_bfloat16 g_qh [M_ * D_],    g_ql [M_ * D_];
__device__ __align__(16) __nv_bfloat16 g_kh [M_ * D_],    g_kl [M_ * D_];
__device__ __align__(16) __nv_bfloat16 g_vh [M_ * D_],    g_vl [M_ * D_];
__device__ __align__(16) __nv_bfloat16 g_ath[M_ * D_],    g_atl[M_ * D_];
__device__ __align__(16) __nv_bfloat16 g_aoh[M_ * D_],    g_aol[M_ * D_];
__device__ __align__(16) __nv_bfloat16 g_hhh[(size_t)M_ * DH_], g_hhl[(size_t)M_ * DH_];

__device__ __forceinline__ float elu1(float x) { return x > 0.f ? x + 1.f : __expf(x); }

__device__ __forceinline__ void split2(float a, float b, uint32_t& hi, uint32_t& lo) {
    __nv_bfloat162 h; h.x = __float2bfloat16(a); h.y = __float2bfloat16(b);
    __nv_bfloat162 l;
    l.x = __float2bfloat16(a - __bfloat162float(h.x));
    l.y = __float2bfloat16(b - __bfloat162float(h.y));
    hi = *(uint32_t*)&h; lo = *(uint32_t*)&l;
}

// ================= mma helpers ===================================================
__device__ __forceinline__ void cp16(void* dst, const void* src) {
    uint32_t d = (uint32_t)__cvta_generic_to_shared(dst);
    asm volatile("cp.async.cg.shared.global [%0], [%1], 16;" :: "r"(d), "l"(src));
}

#define LDSM4(f, p) do { \
    uint32_t a_ = (uint32_t)__cvta_generic_to_shared(p); \
    asm volatile("ldmatrix.sync.aligned.m8n8.x4.shared.b16 {%0,%1,%2,%3}, [%4];" \
        : "=r"(f[0]), "=r"(f[1]), "=r"(f[2]), "=r"(f[3]) : "r"(a_)); \
} while (0)

#define LDSM4T(f, p) do { \
    uint32_t a_ = (uint32_t)__cvta_generic_to_shared(p); \
    asm volatile("ldmatrix.sync.aligned.m8n8.x4.trans.shared.b16 {%0,%1,%2,%3}, [%4];" \
        : "=r"(f[0]), "=r"(f[1]), "=r"(f[2]), "=r"(f[3]) : "r"(a_)); \
} while (0)

#define MMA16816(d, a, b0, b1) \
    asm volatile("mma.sync.aligned.m16n8k16.row.col.f32.bf16.bf16.f32 " \
        "{%0,%1,%2,%3}, {%4,%5,%6,%7}, {%8,%9}, {%0,%1,%2,%3};" \
        : "+f"(d[0]), "+f"(d[1]), "+f"(d[2]), "+f"(d[3]) \
        : "r"(a[0]), "r"(a[1]), "r"(a[2]), "r"(a[3]), "r"(b0), "r"(b1))

// ================= bf16x3 tensor-core GEMM, CTA 128x256, warp 64x64 ==============
#define SA_STRIDE 40     // 32 + 8 pad (bf16 elems)
#define SB_STRIDE 264    // 256 + 8 pad
#define SA_STAGE  (128*SA_STRIDE)   // 5120 elems
#define SB_STAGE  (32*SB_STRIDE)    // 8448 elems
#define BGEMM_SMEM ((2*SA_STAGE*2 + 2*SB_STAGE*2) * 2)  // 108544 bytes

__device__ __forceinline__ void bg_load_stage(
    const __nv_bfloat16* __restrict__ Ahg, const __nv_bfloat16* __restrict__ Alg,
    const __nv_bfloat16* __restrict__ Bhg, const __nv_bfloat16* __restrict__ Blg,
    __nv_bfloat16* sAh, __nv_bfloat16* sAl, __nv_bfloat16* sBh, __nv_bfloat16* sBl,
    int tid, size_t m0, size_t n0, int Kk, int Nn, int k0)
{
    // A: 128 rows x 32 cols = 512 16B-chunks per array (2/thread)
#pragma unroll
    for (int it = 0; it < 2; it++) {
        int c = it*256 + tid;
        int r = c >> 2, col = (c & 3) << 3;
        size_t go = (m0 + r) * (size_t)Kk + k0 + col;
        cp16(sAh + r * SA_STRIDE + col, Ahg + go);
        cp16(sAl + r * SA_STRIDE + col, Alg + go);
    }
    // B: 32 rows x 256 cols = 1024 chunks per array (4/thread)
#pragma unroll
    for (int it = 0; it < 4; it++) {
        int c = it*256 + tid;
        int r = c >> 5, col = (c & 31) << 3;
        size_t go = (size_t)(k0 + r) * Nn + n0 + col;
        cp16(sBh + r * SB_STRIDE + col, Bhg + go);
        cp16(sBl + r * SB_STRIDE + col, Blg + go);
    }
    asm volatile("cp.async.commit_group;");
}

__global__ void __launch_bounds__(256)
bgemm_kernel(const __nv_bfloat16* __restrict__ Ahg, const __nv_bfloat16* __restrict__ Alg,
             const __nv_bfloat16* __restrict__ Bhg, const __nv_bfloat16* __restrict__ Blg,
             int Kk, int Nn,
             const float* __restrict__ bias, int relu, const float* __restrict__ resid,
             float* __restrict__ C,
             __nv_bfloat16* __restrict__ Ch, __nv_bfloat16* __restrict__ Cl)
{
    extern __shared__ __nv_bfloat16 smem[];
    __nv_bfloat16* sAh = smem;
    __nv_bfloat16* sAl = smem + 2*SA_STAGE;
    __nv_bfloat16* sBh = smem + 4*SA_STAGE;
    __nv_bfloat16* sBl = smem + 4*SA_STAGE + 2*SB_STAGE;

    int tid = threadIdx.x;
    int warp = tid >> 5, lane = tid & 31;
    int wm = warp >> 2, wn = warp & 3;          // 2 x 4 warp grid, warp tile 64x64
    size_t m0 = (size_t)blockIdx.y * 128;
    size_t n0 = (size_t)blockIdx.x * 256;

    float acc[4][8][4];
#pragma unroll
    for (int i = 0; i < 4; i++)
#pragma unroll
        for (int j = 0; j < 8; j++)
#pragma unroll
            for (int t = 0; t < 4; t++) acc[i][j][t] = 0.f;

    int nk = Kk >> 5;
    bg_load_stage(Ahg, Alg, Bhg, Blg, sAh, sAl, sBh, sBl, tid, m0, n0, Kk, Nn, 0);

    for (int kt = 0; kt < nk; kt++) {
        int cur = kt & 1;
        if (kt + 1 < nk) {
            bg_load_stage(Ahg, Alg, Bhg, Blg,
                          sAh + ((kt+1)&1)*SA_STAGE, sAl + ((kt+1)&1)*SA_STAGE,
                          sBh + ((kt+1)&1)*SB_STAGE, sBl + ((kt+1)&1)*SB_STAGE,
                          tid, m0, n0, Kk, Nn, (kt+1)*32);
            asm volatile("cp.async.wait_group 1;");
        } else {
            asm volatile("cp.async.wait_group 0;");
        }
        __syncthreads();

        __nv_bfloat16* ah = sAh + cur*SA_STAGE;
        __nv_bfloat16* al = sAl + cur*SA_STAGE;
        __nv_bfloat16* bh = sBh + cur*SB_STAGE;
        __nv_bfloat16* bl = sBl + cur*SB_STAGE;

#pragma unroll
        for (int k16 = 0; k16 < 32; k16 += 16) {
            uint32_t afh[4][4], afl[4][4], bfh[4][4], bfl[4][4];
#pragma unroll
            for (int mi = 0; mi < 4; mi++) {
                const __nv_bfloat16* pa = ah + (size_t)(wm*64 + mi*16 + (lane & 15)) * SA_STRIDE
                                             + k16 + (lane >> 4) * 8;
                LDSM4(afh[mi], pa);
                const __nv_bfloat16* pl = al + (size_t)(wm*64 + mi*16 + (lane & 15)) * SA_STRIDE
                                             + k16 + (lane >> 4) * 8;
                LDSM4(afl[mi], pl);
            }
#pragma unroll
            for (int nb = 0; nb < 4; nb++) {
                const __nv_bfloat16* pb = bh + (size_t)(k16 + (lane & 15)) * SB_STRIDE
                                             + wn*64 + nb*16 + (lane >> 4) * 8;
                LDSM4T(bfh[nb], pb);
                const __nv_bfloat16* pq = bl + (size_t)(k16 + (lane & 15)) * SB_STRIDE
                                             + wn*64 + nb*16 + (lane >> 4) * 8;
                LDSM4T(bfl[nb], pq);
            }
#pragma unroll
            for (int mi = 0; mi < 4; mi++)
#pragma unroll
                for (int ni = 0; ni < 8; ni++) {
                    int nb = ni >> 1, sel = (ni & 1) * 2;
                    MMA16816(acc[mi][ni], afh[mi], bfh[nb][sel], bfh[nb][sel+1]);
                    MMA16816(acc[mi][ni], afh[mi], bfl[nb][sel], bfl[nb][sel+1]);
                    MMA16816(acc[mi][ni], afl[mi], bfh[nb][sel], bfh[nb][sel+1]);
                }
        }
        __syncthreads();
    }

    // epilogue
#pragma unroll
    for (int mi = 0; mi < 4; mi++)
#pragma unroll
        for (int ni = 0; ni < 8; ni++) {
            int col = wn*64 + ni*8 + (lane & 3) * 2;
#pragma unroll
            for (int hh = 0; hh < 2; hh++) {
                int row = wm*64 + mi*16 + (lane >> 2) + hh*8;
                float v0 = acc[mi][ni][hh*2], v1 = acc[mi][ni][hh*2+1];
                size_t o = (m0 + row) * (size_t)Nn + n0 + col;
                if (bias) { v0 += bias[n0+col]; v1 += bias[n0+col+1]; }
                if (resid) { v0 += resid[o]; v1 += resid[o+1]; }
                if (relu) { v0 = fmaxf(v0, 0.f); v1 = fmaxf(v1, 0.f); }
                if (C) { C[o] = v0; C[o+1] = v1; }
                if (Ch) {
                    uint32_t hp, lp;
                    split2(v0, v1, hp, lp);
                    *(uint32_t*)(Ch + o) = hp;
                    *(uint32_t*)(Cl + o) = lp;
                }
            }
        }
}

// ---------------- fp32 -> bf16 hi/lo split --------------------------------------
__global__ void __launch_bounds__(256)
split_kernel(const float4* __restrict__ in, __nv_bfloat162* __restrict__ hi,
             __nv_bfloat162* __restrict__ lo, int nquads)
{
    int i = blockIdx.x * 256 + threadIdx.x;
    if (i >= nquads) return;
    float4 v = in[i];
    uint32_t h0, l0, h1, l1;
    split2(v.x, v.y, h0, l0);
    split2(v.z, v.w, h1, l1);
    hi[2*i]   = *(__nv_bfloat162*)&h0;
    hi[2*i+1] = *(__nv_bfloat162*)&h1;
    lo[2*i]   = *(__nv_bfloat162*)&l0;
    lo[2*i+1] = *(__nv_bfloat162*)&l1;
}

// ================= flash attention (bf16x3 mma) ==================================
#define AT_STR 136
#define AT_TILE (64*AT_STR)
#define ATTN_SMEM_BYTES (6 * AT_TILE * 2)

__global__ void __launch_bounds__(128)
attn_mma_kernel(const __nv_bfloat16* __restrict__ qh, const __nv_bfloat16* __restrict__ ql,
                const __nv_bfloat16* __restrict__ kh, const __nv_bfloat16* __restrict__ kl,
                const __nv_bfloat16* __restrict__ vh, const __nv_bfloat16* __restrict__ vl,
                float* __restrict__ att)
{
    extern __shared__ __nv_bfloat16 sm[];
    __nv_bfloat16* Qh = sm;
    __nv_bfloat16* Ql = sm + AT_TILE;
    __nv_bfloat16* Kh = sm + 2*AT_TILE;
    __nv_bfloat16* Kl = sm + 3*AT_TILE;
    __nv_bfloat16* Vh = sm + 4*AT_TILE;
    __nv_bfloat16* Vl = sm + 5*AT_TILE;

    int qt = blockIdx.x, seg = blockIdx.y, bh = blockIdx.z;
    int b = bh >> 4, h = bh & 15;
    int tid = threadIdx.x, warp = tid >> 5, lane = tid & 31;
    const float scale = 0.08838834764831845f;
    size_t base = ((size_t)(b*S_ + seg*SEG_) * H_ + h) * DK_;

#pragma unroll
    for (int it = 0; it < 8; it++) {
        int e = it*128 + tid, r = e >> 4, c8 = (e & 15) << 3;
        size_t go = base + (size_t)(qt*64 + r)*2048 + c8;
        *(uint4*)(Qh + r*AT_STR + c8) = *(const uint4*)(qh + go);
        *(uint4*)(Ql + r*AT_STR + c8) = *(const uint4*)(ql + go);
    }

    float o[16][4];
#pragma unroll
    for (int t = 0; t < 16; t++)
#pragma unroll
        for (int j = 0; j < 4; j++) o[t][j] = 0.f;
    float m0 = -1e30f, m1 = -1e30f, l0 = 0.f, l1 = 0.f;
    int r0g = qt*64 + warp*16 + (lane >> 2);
    int r1g = r0g + 8;

    for (int kt = 0; kt <= qt; kt++) {
        __syncthreads();
#pragma unroll
        for (int it = 0; it < 8; it++) {
            int e = it*128 + tid, r = e >> 4, c8 = (e & 15) << 3;
            size_t go = base + (size_t)(kt*64 + r)*2048 + c8;
            *(uint4*)(Kh + r*AT_STR + c8) = *(const uint4*)(kh + go);
            *(uint4*)(Kl + r*AT_STR + c8) = *(const uint4*)(kl + go);
            *(uint4*)(Vh + r*AT_STR + c8) = *(const uint4*)(vh + go);
            *(uint4*)(Vl + r*AT_STR + c8) = *(const uint4*)(vl + go);
        }
        __syncthreads();

        float s[8][4];
#pragma unroll
        for (int t = 0; t < 8; t++)
#pragma unroll
            for (int j = 0; j < 4; j++) s[t][j] = 0.f;

#pragma unroll
        for (int kk = 0; kk < 8; kk++) {
            uint32_t qa[4], qb[4];
            LDSM4(qa, Qh + (size_t)(warp*16 + (lane & 15))*AT_STR + kk*16 + (lane >> 4)*8);
            LDSM4(qb, Ql + (size_t)(warp*16 + (lane & 15))*AT_STR + kk*16 + (lane >> 4)*8);
#pragma unroll
            for (int ng = 0; ng < 4; ng++) {
                uint32_t kfh[4], kfl[4];
                LDSM4(kfh, Kh + (size_t)(ng*16 + (lane & 15))*AT_STR + kk*16 + (lane >> 4)*8);
                LDSM4(kfl, Kl + (size_t)(ng*16 + (lane & 15))*AT_STR + kk*16 + (lane >> 4)*8);
                MMA16816(s[2*ng],   qa, kfh[0], kfh[2]);
                MMA16816(s[2*ng],   qa, kfl[0], kfl[2]);
                MMA16816(s[2*ng],   qb, kfh[0], kfh[2]);
                MMA16816(s[2*ng+1], qa, kfh[1], kfh[3]);
                MMA16816(s[2*ng+1], qa, kfl[1], kfl[3]);
                MMA16816(s[2*ng+1], qb, kfh[1], kfh[3]);
            }
        }

        float mx0 = -1e30f, mx1 = -1e30f;
#pragma unroll
        for (int t = 0; t < 8; t++) {
            int colb = kt*64 + t*8 + (lane & 3)*2;
            float a0 = s[t][0]*scale, a1 = s[t][1]*scale;
            float a2 = s[t][2]*scale, a3 = s[t][3]*scale;
            if (kt == qt) {
                if (colb     > r0g) a0 = -1e30f;
                if (colb + 1 > r0g) a1 = -1e30f;
                if (colb     > r1g) a2 = -1e30f;
                if (colb + 1 > r1g) a3 = -1e30f;
            }
            s[t][0] = a0; s[t][1] = a1; s[t][2] = a2; s[t][3] = a3;
            mx0 = fmaxf(mx0, fmaxf(a0, a1));
            mx1 = fmaxf(mx1, fmaxf(a2, a3));
        }
        mx0 = fmaxf(mx0, __shfl_xor_sync(0xffffffffu, mx0, 1));
        mx0 = fmaxf(mx0, __shfl_xor_sync(0xffffffffu, mx0, 2));
        mx1 = fmaxf(mx1, __shfl_xor_sync(0xffffffffu, mx1, 1));
        mx1 = fmaxf(mx1, __shfl_xor_sync(0xffffffffu, mx1, 2));
        float m0n = fmaxf(m0, mx0), m1n = fmaxf(m1, mx1);
        float rc0 = __expf(m0 - m0n), rc1 = __expf(m1 - m1n);
        float sum0 = 0.f, sum1 = 0.f;
#pragma unroll
        for (int t = 0; t < 8; t++) {
            s[t][0] = __expf(s[t][0] - m0n); sum0 += s[t][0];
            s[t][1] = __expf(s[t][1] - m0n); sum0 += s[t][1];
            s[t][2] = __expf(s[t][2] - m1n); sum1 += s[t][2];
            s[t][3] = __expf(s[t][3] - m1n); sum1 += s[t][3];
        }
        sum0 += __shfl_xor_sync(0xffffffffu, sum0, 1);
        sum0 += __shfl_xor_sync(0xffffffffu, sum0, 2);
        sum1 += __shfl_xor_sync(0xffffffffu, sum1, 1);
        sum1 += __shfl_xor_sync(0xffffffffu, sum1, 2);
        l0 = l0*rc0 + sum0;  l1 = l1*rc1 + sum1;
        m0 = m0n;  m1 = m1n;
#pragma unroll
        for (int t = 0; t < 16; t++) {
            o[t][0] *= rc0; o[t][1] *= rc0; o[t][2] *= rc1; o[t][3] *= rc1;
        }

#pragma unroll
        for (int kk = 0; kk < 4; kk++) {
            uint32_t ah[4], al[4];
            split2(s[2*kk][0],   s[2*kk][1],   ah[0], al[0]);
            split2(s[2*kk][2],   s[2*kk][3],   ah[1], al[1]);
            split2(s[2*kk+1][0], s[2*kk+1][1], ah[2], al[2]);
            split2(s[2*kk+1][2], s[2*kk+1][3], ah[3], al[3]);
#pragma unroll
            for (int dg = 0; dg < 8; dg++) {
                uint32_t vfh[4], vfl[4];
                LDSM4T(vfh, Vh + (size_t)(kk*16 + (lane & 15))*AT_STR + dg*16 + (lane >> 4)*8);
                LDSM4T(vfl, Vl + (size_t)(kk*16 + (lane & 15))*AT_STR + dg*16 + (lane >> 4)*8);
                MMA16816(o[2*dg],   ah, vfh[0], vfh[1]);
                MMA16816(o[2*dg],   al, vfh[0], vfh[1]);
                MMA16816(o[2*dg],   ah, vfl[0], vfl[1]);
                MMA16816(o[2*dg+1], ah, vfh[2], vfh[3]);
                MMA16816(o[2*dg+1], al, vfh[2], vfh[3]);
                MMA16816(o[2*dg+1], ah, vfl[2], vfl[3]);
            }
        }
    }

    float inv0 = 1.f / l0, inv1 = 1.f / l1;
#pragma unroll
    for (int t = 0; t < 16; t++) {
        size_t ro = base + (size_t)(qt*64 + warp*16 + (lane >> 2))*2048 + t*8 + (lane & 3)*2;
        float2 w0; w0.x = o[t][0]*inv0; w0.y = o[t][1]*inv0;
        float2 w1; w1.x = o[t][2]*inv1; w1.y = o[t][3]*inv1;
        *(float2*)(att + ro)          = w0;
        *(float2*)(att + ro + 8*2048) = w1;
    }
}

// ================= memory update: U = sig(K)^T V (bf16x3 mma) ====================
#define MU_KSTR 72
#define MU_KTILE (128*MU_KSTR)
#define MU_VSTR 136
#define MU_VTILE (64*MU_VSTR)
#define MEMUPD_SMEM ((2*MU_KTILE + 2*MU_VTILE) * 2)

__global__ void __launch_bounds__(256)
memupd_mma_kernel(const __nv_bfloat16* __restrict__ kh, const __nv_bfloat16* __restrict__ kl,
                  const __nv_bfloat16* __restrict__ vh, const __nv_bfloat16* __restrict__ vl,
                  float* __restrict__ U, float* __restrict__ zU)
{
    extern __shared__ __nv_bfloat16 sm[];
    __nv_bfloat16* sKh = sm;
    __nv_bfloat16* sKl = sm + MU_KTILE;
    __nv_bfloat16* sVh = sm + 2*MU_KTILE;
    __nv_bfloat16* sVl = sm + 2*MU_KTILE + MU_VTILE;
    __shared__ float zsm[128];

    int seg = blockIdx.x & 7, bhx = blockIdx.x >> 3;
    int b = bhx >> 4, h = bhx & 15;
    int tid = threadIdx.x, warp = tid >> 5, lane = tid & 31;
    int wm = warp >> 1, wn = warp & 1;
    size_t base = ((size_t)(b*S_ + seg*SEG_) * H_ + h) * DK_;

    if (tid < 128) zsm[tid] = 0.f;

    float acc[2][8][4];
#pragma unroll
    for (int i = 0; i < 2; i++)
#pragma unroll
        for (int j = 0; j < 8; j++)
#pragma unroll
            for (int t = 0; t < 4; t++) acc[i][j][t] = 0.f;

    for (int st = 0; st < 8; st++) {
        int s0 = st * 64;
#pragma unroll
        for (int it = 0; it < 16; it++) {
            int e = it*256 + tid, s = e >> 6, c2 = e & 63;
            size_t go = base + (size_t)(s0 + s)*2048 + 2*c2;
            __nv_bfloat162 h2 = *(const __nv_bfloat162*)(kh + go);
            __nv_bfloat162 l2 = *(const __nv_bfloat162*)(kl + go);
            float f0 = elu1(__bfloat162float(h2.x) + __bfloat162float(l2.x));
            float f1 = elu1(__bfloat162float(h2.y) + __bfloat162float(l2.y));
            __nv_bfloat16 h0 = __float2bfloat16(f0), h1 = __float2bfloat16(f1);
            sKh[(2*c2)  *MU_KSTR + s] = h0;
            sKh[(2*c2+1)*MU_KSTR + s] = h1;
            sKl[(2*c2)  *MU_KSTR + s] = __float2bfloat16(f0 - __bfloat162float(h0));
            sKl[(2*c2+1)*MU_KSTR + s] = __float2bfloat16(f1 - __bfloat162float(h1));
        }
#pragma unroll
        for (int it = 0; it < 4; it++) {
            int e = it*256 + tid, r = e >> 4, c8 = (e & 15) << 3;
            size_t go = base + (size_t)(s0 + r)*2048 + c8;
            *(uint4*)(sVh + r*MU_VSTR + c8) = *(const uint4*)(vh + go);
            *(uint4*)(sVl + r*MU_VSTR + c8) = *(const uint4*)(vl + go);
        }
        __syncthreads();

        if (tid < 128) {
            float zz = 0.f;
#pragma unroll 4
            for (int s = 0; s < 64; s++)
                zz += __bfloat162float(sKh[tid*MU_KSTR + s])
                    + __bfloat162float(sKl[tid*MU_KSTR + s]);
            zsm[tid] += zz;
        }

#pragma unroll
        for (int kk = 0; kk < 4; kk++) {
            uint32_t ah[2][4], al[2][4];
#pragma unroll
            for (int mi = 0; mi < 2; mi++) {
                LDSM4(ah[mi], sKh + (size_t)(wm*32 + mi*16 + (lane & 15))*MU_KSTR + kk*16 + (lane >> 4)*8);
                LDSM4(al[mi], sKl + (size_t)(wm*32 + mi*16 + (lane & 15))*MU_KSTR + kk*16 + (lane >> 4)*8);
            }
#pragma unroll
            for (int ng = 0; ng < 4; ng++) {
                uint32_t bh4[4], bl4[4];
                LDSM4T(bh4, sVh + (size_t)(kk*16 + (lane & 15))*MU_VSTR + wn*64 + ng*16 + (lane >> 4)*8);
                LDSM4T(bl4, sVl + (size_t)(kk*16 + (lane & 15))*MU_VSTR + wn*64 + ng*16 + (lane >> 4)*8);
#pragma unroll
                for (int mi = 0; mi < 2; mi++) {
                    MMA16816(acc[mi][2*ng],   ah[mi], bh4[0], bh4[1]);
                    MMA16816(acc[mi][2*ng],   al[mi], bh4[0], bh4[1]);
                    MMA16816(acc[mi][2*ng],   ah[mi], bl4[0], bl4[1]);
                    MMA16816(acc[mi][2*ng+1], ah[mi], bh4[2], bh4[3]);
                    MMA16816(acc[mi][2*ng+1], al[mi], bh4[2], bh4[3]);
                    MMA16816(acc[mi][2*ng+1], ah[mi], bl4[2], bl4[3]);
                }
            }
        }
        __syncthreads();
    }

    size_t ob = (size_t)blockIdx.x * (DK_*DV_);
#pragma unroll
    for (int mi = 0; mi < 2; mi++)
#pragma unroll
        for (int ni = 0; ni < 8; ni++) {
            int col = wn*64 + ni*8 + (lane & 3)*2;
#pragma unroll
            for (int hh = 0; hh < 2; hh++) {
                int row = wm*32 + mi*16 + (lane >> 2) + hh*8;
                float2 w; w.x = acc[mi][ni][hh*2]; w.y = acc[mi][ni][hh*2+1];
                *(float2*)(U + ob + (size_t)row*128 + col) = w;
            }
        }
    if (tid < 128) zU[(size_t)blockIdx.x*128 + tid] = zsm[tid];
}

// ---------------- exclusive prefix over segments --------------------------------
__global__ void __launch_bounds__(256)
prefix_kernel(const float* __restrict__ U, const float* __restrict__ zU,
              float* __restrict__ Mem, float* __restrict__ Z)
{
    int bh = blockIdx.x, tid = threadIdx.x;
    for (int idx = tid; idx < DK_*DV_; idx += 256) {
        float run = 0.f;
#pragma unroll
        for (int sg = 0; sg < NSEG_; sg++) {
            size_t o = ((size_t)(bh*NSEG_ + sg)) * (DK_*DV_) + idx;
            Mem[o] = run;
            run += U[o];
        }
    }
    if (tid < 128) {
        float run = 1.f / 128.f;
#pragma unroll
        for (int sg = 0; sg < NSEG_; sg++) {
            size_t o = (size_t)(bh*NSEG_ + sg) * 128 + tid;
            Z[o] = run;
            run += zU[o];
        }
    }
}

// ================= retrieval + gate combine (bf16x3 mma) =========================
#define RT_STR 136
#define RT_TILE (128*RT_STR)
#define RETR_SMEM (4 * RT_TILE * 2)

__global__ void __launch_bounds__(256)
retrieve_mma_kernel(const __nv_bfloat16* __restrict__ qh, const __nv_bfloat16* __restrict__ ql,
                    const float* __restrict__ Mem, const float* __restrict__ Z,
                    const float* __restrict__ betas, const float* __restrict__ attdot,
                    __nv_bfloat16* __restrict__ ath, __nv_bfloat16* __restrict__ atl)
{
    extern __shared__ __nv_bfloat16 sm[];
    __nv_bfloat16* Mh = sm;
    __nv_bfloat16* Ml = sm + RT_TILE;
    __nv_bfloat16* Sh = sm + 2*RT_TILE;
    __nv_bfloat16* Sl = sm + 3*RT_TILE;
    __shared__ float den[128], zz[128], gate[128];

    int seg = blockIdx.x & 7, bhx = blockIdx.x >> 3;
    int b = bhx >> 4, h = bhx & 15;
    int tid = threadIdx.x, warp = tid >> 5, lane = tid & 31;
    size_t base = ((size_t)(b*S_ + seg*SEG_) * H_ + h) * DK_;
    size_t mb = (size_t)blockIdx.x * 16384;

    if (tid < 128) {
        gate[tid] = 1.f / (1.f + __expf(-betas[h*128 + tid]));
        zz[tid]   = Z[(size_t)blockIdx.x*128 + tid];
    }
#pragma unroll
    for (int it = 0; it < 16; it++) {
        int e = it*256 + tid, r = e >> 5, c4 = (e & 31) << 2;
        float4 v = *(const float4*)(Mem + mb + (size_t)r*128 + c4);
        uint32_t h0, l0, h1, l1;
        split2(v.x, v.y, h0, l0);
        split2(v.z, v.w, h1, l1);
        *(uint32_t*)(Mh + r*RT_STR + c4)     = h0;
        *(uint32_t*)(Mh + r*RT_STR + c4 + 2) = h1;
        *(uint32_t*)(Ml + r*RT_STR + c4)     = l0;
        *(uint32_t*)(Ml + r*RT_STR + c4 + 2) = l1;
    }
    __syncthreads();

    for (int ch = 0; ch < 4; ch++) {
        int s0 = ch * 128;
#pragma unroll
        for (int it = 0; it < 32; it++) {
            int e = it*256 + tid, s = e >> 6, c2 = e & 63;
            size_t go = base + (size_t)(s0 + s)*2048 + 2*c2;
            __nv_bfloat162 h2 = *(const __nv_bfloat162*)(qh + go);
            __nv_bfloat162 l2 = *(const __nv_bfloat162*)(ql + go);
            float f0 = elu1(__bfloat162float(h2.x) + __bfloat162float(l2.x));
            float f1 = elu1(__bfloat162float(h2.y) + __bfloat162float(l2.y));
            uint32_t hp, lp;
            split2(f0, f1, hp, lp);
            *(uint32_t*)(Sh + s*RT_STR + 2*c2) = hp;
            *(uint32_t*)(Sl + s*RT_STR + 2*c2) = lp;
        }
        __syncthreads();
        if (tid < 128) {
            float d = 0.f;
#pragma unroll 4
            for (int dk = 0; dk < 128; dk++)
                d += (__bfloat162float(Sh[tid*RT_STR + dk])
                    + __bfloat162float(Sl[tid*RT_STR + dk])) * zz[dk];
            den[tid] = d;
        }
        __syncthreads();

        float o[16][4];
#pragma unroll
        for (int t = 0; t < 16; t++)
#pragma unroll
            for (int j = 0; j < 4; j++) o[t][j] = 0.f;

#pragma unroll
        for (int kk = 0; kk < 8; kk++) {
            uint32_t qa[4], qb[4];
            LDSM4(qa, Sh + (size_t)(warp*16 + (lane & 15))*RT_STR + kk*16 + (lane >> 4)*8);
            LDSM4(qb, Sl + (size_t)(warp*16 + (lane & 15))*RT_STR + kk*16 + (lane >> 4)*8);
#pragma unroll
            for (int ng = 0; ng < 8; ng++) {
                uint32_t mh4[4], ml4[4];
                LDSM4T(mh4, Mh + (size_t)(kk*16 + (lane & 15))*RT_STR + ng*16 + (lane >> 4)*8);
                LDSM4T(ml4, Ml + (size_t)(kk*16 + (lane & 15))*RT_STR + ng*16 + (lane >> 4)*8);
                MMA16816(o[2*ng],   qa, mh4[0], mh4[1]);
                MMA16816(o[2*ng],   qb, mh4[0], mh4[1]);
                MMA16816(o[2*ng],   qa, ml4[0], ml4[1]);
                MMA16816(o[2*ng+1], qa, mh4[2], mh4[3]);
                MMA16816(o[2*ng+1], qb, mh4[2], mh4[3]);
                MMA16816(o[2*ng+1], qa, ml4[2], ml4[3]);
            }
        }

        float inv0 = 1.f / den[warp*16 + (lane >> 2)];
        float inv1 = 1.f / den[warp*16 + (lane >> 2) + 8];
#pragma unroll
        for (int t = 0; t < 16; t++) {
            int col = t*8 + (lane & 3)*2;
            float g0 = gate[col], g1 = gate[col+1];
            size_t ro = base + (size_t)(s0 + warp*16 + (lane >> 2))*2048 + col;
            float2 d0 = *(const float2*)(attdot + ro);
            float2 d1 = *(const float2*)(attdot + ro + 8*2048);
            float v0 = g0*(o[t][0]*inv0) + (1.f - g0)*d0.x;
            float v1 = g1*(o[t][1]*inv0) + (1.f - g1)*d0.y;
            float v2 = g0*(o[t][2]*inv1) + (1.f - g0)*d1.x;
            float v3 = g1*(o[t][3]*inv1) + (1.f - g1)*d1.y;
            uint32_t hp, lp;
            split2(v0, v1, hp, lp);
            *(uint32_t*)(ath + ro) = hp;
            *(uint32_t*)(atl + ro) = lp;
            split2(v2, v3, hp, lp);
            *(uint32_t*)(ath + ro + 8*2048) = hp;
            *(uint32_t*)(atl + ro + 8*2048) = lp;
        }
        __syncthreads();
    }
}

// ---------------- LayerNorm -----------------------------------------------------
__global__ void __launch_bounds__(256)
ln_kernel(const float* __restrict__ y, const float* __restrict__ gg,
          const float* __restrict__ bb, float* __restrict__ out)
{
    size_t row = blockIdx.x;
    const float* p = y + row * D_;
    int tid = threadIdx.x;
    float4 v0 = *(const float4*)(p + tid*8);
    float4 v1 = *(const float4*)(p + tid*8 + 4);
    float s  = v0.x+v0.y+v0.z+v0.w + v1.x+v1.y+v1.z+v1.w;
    float s2 = v0.x*v0.x+v0.y*v0.y+v0.z*v0.z+v0.w*v0.w
             + v1.x*v1.x+v1.y*v1.y+v1.z*v1.z+v1.w*v1.w;
#pragma unroll
    for (int o = 16; o >= 1; o >>= 1) {
        s  += __shfl_xor_sync(0xffffffffu, s, o);
        s2 += __shfl_xor_sync(0xffffffffu, s2, o);
    }
    __shared__ float red[16];
    __shared__ float stat[2];
    int warp = tid >> 5, lane = tid & 31;
    if (lane == 0) { red[warp] = s; red[warp + 8] = s2; }
    __syncthreads();
    if (tid == 0) {
        float S = 0.f, S2 = 0.f;
#pragma unroll
        for (int w = 0; w < 8; w++) { S += red[w]; S2 += red[w + 8]; }
        float mean = S / (float)D_;
        float var  = S2 / (float)D_ - mean*mean;
        stat[0] = mean;
        stat[1] = rsqrtf(var + 1e-5f);
    }
    __syncthreads();
    float mean = stat[0], inv = stat[1];
    float4 g0 = *(const float4*)(gg + tid*8), g1 = *(const float4*)(gg + tid*8 + 4);
    float4 b0 = *(const float4*)(bb + tid*8), b1 = *(const float4*)(bb + tid*8 + 4);
    float4 o0, o1;
    o0.x = (v0.x-mean)*inv*g0.x + b0.x; o0.y = (v0.y-mean)*inv*g0.y + b0.y;
    o0.z = (v0.z-mean)*inv*g0.z + b0.z; o0.w = (v0.w-mean)*inv*g0.w + b0.w;
    o1.x = (v1.x-mean)*inv*g1.x + b1.x; o1.y = (v1.y-mean)*inv*g1.y + b1.y;
    o1.z = (v1.z-mean)*inv*g1.z + b1.z; o1.w = (v1.w-mean)*inv*g1.w + b1.w;
    *(float4*)(out + row*D_ + tid*8)     = o0;
    *(float4*)(out + row*D_ + tid*8 + 4) = o1;
}

// ---------------- launch --------------------------------------------------------
static inline void split_launch(const float* src, __nv_bfloat16* hi, __nv_bfloat16* lo,
                                size_t nelems)
{
    int nq = (int)(nelems / 4);
    split_kernel<<<(nq + 255)/256, 256>>>((const float4*)src,
                                          (__nv_bfloat162*)hi, (__nv_bfloat162*)lo, nq);
}

extern "C" void kernel_launch(void* const* d_in, const int* in_sizes, int n_in,
                              void* d_out, int out_size)
{
    const float* x     = (const float*)d_in[0];
    const float* Wq    = (const float*)d_in[1];
    const float* Wk    = (const float*)d_in[2];
    const float* Wv    = (const float*)d_in[3];
    const float* Wo    = (const float*)d_in[4];
    const float* betas = (const float*)d_in[5];
    const float* W1    = (const float*)d_in[6];
    const float* b1    = (const float*)d_in[7];
    const float* W2    = (const float*)d_in[8];
    const float* b2    = (const float*)d_in[9];
    const float* ln_g  = (const float*)d_in[10];
    const float* ln_b  = (const float*)d_in[11];
    float* out = (float*)d_out;

    float *att_, *y_, *U_, *zU_, *mem_, *z_;
    cudaGetSymbolAddress((void**)&att_, g_att);
    cudaGetSymbolAddress((void**)&y_,   g_y);
    cudaGetSymbolAddress((void**)&U_,   g_U);
    cudaGetSymbolAddress((void**)&zU_,  g_zU);
    cudaGetSymbolAddress((void**)&mem_, g_mem);
    cudaGetSymbolAddress((void**)&z_,   g_z);

    __nv_bfloat16 *xh,*xl,*wqh,*wql,*wkh,*wkl,*wvh,*wvl,*woh,*wol,
                  *w1h,*w1l,*w2h,*w2l,*ath,*atl,*aoh,*aol,*hhh,*hhl,
                  *qh,*ql,*kh,*kl,*vh,*vl;
    cudaGetSymbolAddress((void**)&xh,  g_xh);  cudaGetSymbolAddress((void**)&xl,  g_xl);
    cudaGetSymbolAddress((void**)&wqh, g_wqh); cudaGetSymbolAddress((void**)&wql, g_wql);
    cudaGetSymbolAddress((void**)&wkh, g_wkh); cudaGetSymbolAddress((void**)&wkl, g_wkl);
    cudaGetSymbolAddress((void**)&wvh, g_wvh); cudaGetSymbolAddress((void**)&wvl, g_wvl);
    cudaGetSymbolAddress((void**)&woh, g_woh); cudaGetSymbolAddress((void**)&wol, g_wol);
    cudaGetSymbolAddress((void**)&w1h, g_w1h); cudaGetSymbolAddress((void**)&w1l, g_w1l);
    cudaGetSymbolAddress((void**)&w2h, g_w2h); cudaGetSymbolAddress((void**)&w2l, g_w2l);
    cudaGetSymbolAddress((void**)&ath, g_ath); cudaGetSymbolAddress((void**)&atl, g_atl);
    cudaGetSymbolAddress((void**)&aoh, g_aoh); cudaGetSymbolAddress((void**)&aol, g_aol);
    cudaGetSymbolAddress((void**)&hhh, g_hhh); cudaGetSymbolAddress((void**)&hhl, g_hhl);
    cudaGetSymbolAddress((void**)&qh,  g_qh);  cudaGetSymbolAddress((void**)&ql,  g_ql);
    cudaGetSymbolAddress((void**)&kh,  g_kh);  cudaGetSymbolAddress((void**)&kl,  g_kl);
    cudaGetSymbolAddress((void**)&vh,  g_vh);  cudaGetSymbolAddress((void**)&vl,  g_vl);

    cudaFuncSetAttribute(bgemm_kernel,
        cudaFuncAttributeMaxDynamicSharedMemorySize, BGEMM_SMEM);
    cudaFuncSetAttribute(attn_mma_kernel,
        cudaFuncAttributeMaxDynamicSharedMemorySize, ATTN_SMEM_BYTES);
    cudaFuncSetAttribute(memupd_mma_kernel,
        cudaFuncAttributeMaxDynamicSharedMemorySize, MEMUPD_SMEM);
    cudaFuncSetAttribute(retrieve_mma_kernel,
        cudaFuncAttributeMaxDynamicSharedMemorySize, RETR_SMEM);

    // splits (weights + x)
    split_launch(x,  xh,  xl,  (size_t)M_ * D_);
    split_launch(Wq, wqh, wql, (size_t)D_ * D_);
    split_launch(Wk, wkh, wkl, (size_t)D_ * D_);
    split_launch(Wv, wvh, wvl, (size_t)D_ * D_);
    split_launch(Wo, woh, wol, (size_t)D_ * D_);
    split_launch(W1, w1h, w1l, (size_t)D_ * DH_);
    split_launch(W2, w2h, w2l, (size_t)DH_ * D_);

    dim3 gProj(D_/256, M_/128);          // (8, 64)
    dim3 gMlp1(DH_/256, M_/128);         // (32, 64)

    // QKV projections -> bf16 hi/lo directly
    bgemm_kernel<<<gProj, 256, BGEMM_SMEM>>>(xh, xl, wqh, wql, D_, D_,
        nullptr, 0, nullptr, nullptr, qh, ql);
    bgemm_kernel<<<gProj, 256, BGEMM_SMEM>>>(xh, xl, wkh, wkl, D_, D_,
        nullptr, 0, nullptr, nullptr, kh, kl);
    bgemm_kernel<<<gProj, 256, BGEMM_SMEM>>>(xh, xl, wvh, wvl, D_, D_,
        nullptr, 0, nullptr, nullptr, vh, vl);

    // attention paths (tensor cores)
    attn_mma_kernel<<<dim3(8, 8, 32), 128, ATTN_SMEM_BYTES>>>(qh, ql, kh, kl, vh, vl, att_);
    memupd_mma_kernel<<<256, 256, MEMUPD_SMEM>>>(kh, kl, vh, vl, U_, zU_);
    prefix_kernel<<<32, 256>>>(U_, zU_, mem_, z_);
    retrieve_mma_kernel<<<256, 256, RETR_SMEM>>>(qh, ql, mem_, z_, betas, att_, ath, atl);

    // Wo / MLP chain on tensor cores
    bgemm_kernel<<<gProj, 256, BGEMM_SMEM>>>(ath, atl, woh, wol, D_, D_,
        nullptr, 0, nullptr, nullptr, aoh, aol);
    bgemm_kernel<<<gMlp1, 256, BGEMM_SMEM>>>(aoh, aol, w1h, w1l, D_, DH_,
        b1, 1, nullptr, nullptr, hhh, hhl);
    bgemm_kernel<<<gProj, 256, BGEMM_SMEM>>>(hhh, hhl, w2h, w2l, DH_, D_,
        b2, 0, x, y_, nullptr, nullptr);
    ln_kernel<<<M_, 256>>>(y_, ln_g, ln_b, out);
}

// round 9
// speedup vs baseline: 2.8534x; 2.8534x over previous
#include <cuda_runtime.h>
#include <cuda_fp16.h>
#include <math.h>
#include <stdint.h>

#define B_    2
#define S_    4096
#define D_    2048
#define H_    16
#define DK_   128
#define DV_   128
#define SEG_  512
#define NSEG_ 8
#define DH_   8192
#define M_    (B_*S_)   // 8192 rows

// ---------------- scratch (device globals; no allocation allowed) ----------------
__device__ __align__(16) float g_att[M_ * H_ * DV_];
__device__ __align__(16) float g_y  [M_ * D_];
__device__ __align__(16) float g_U  [B_*H_*NSEG_ * DK_ * DV_];
__device__ __align__(16) float g_zU [B_*H_*NSEG_ * DK_];
__device__ __align__(16) float g_mem[B_*H_*NSEG_ * DK_ * DV_];
__device__ __align__(16) float g_z  [B_*H_*NSEG_ * DK_];
// fp16 tensors
__device__ __align__(16) __half g_x  [M_ * D_];
__device__ __align__(16) __half g_wq [D_ * D_];
__device__ __align__(16) __half g_wk [D_ * D_];
__device__ __align__(16) __half g_wv [D_ * D_];
__device__ __align__(16) __half g_wo [D_ * D_];
__device__ __align__(16) __half g_w1 [D_ * DH_];
__device__ __align__(16) __half g_w2 [DH_ * D_];
__device__ __align__(16) __half g_q  [M_ * D_];
__device__ __align__(16) __half g_k  [M_ * D_];
__device__ __align__(16) __half g_v  [M_ * D_];
__device__ __align__(16) __half g_at [M_ * D_];
__device__ __align__(16) __half g_ao [M_ * D_];
__device__ __align__(16) __half g_hh [(size_t)M_ * DH_];

__device__ __forceinline__ float elu1(float x) { return x > 0.f ? x + 1.f : __expf(x); }

__device__ __forceinline__ uint32_t packh2(float a, float b) {
    __half2 h = __floats2half2_rn(a, b);
    return *(uint32_t*)&h;
}

// ================= mma helpers ===================================================
__device__ __forceinline__ void cp16(void* dst, const void* src) {
    uint32_t d = (uint32_t)__cvta_generic_to_shared(dst);
    asm volatile("cp.async.cg.shared.global [%0], [%1], 16;" :: "r"(d), "l"(src));
}

#define LDSM4(f, p) do { \
    uint32_t a_ = (uint32_t)__cvta_generic_to_shared(p); \
    asm volatile("ldmatrix.sync.aligned.m8n8.x4.shared.b16 {%0,%1,%2,%3}, [%4];" \
        : "=r"(f[0]), "=r"(f[1]), "=r"(f[2]), "=r"(f[3]) : "r"(a_)); \
} while (0)

#define LDSM4T(f, p) do { \
    uint32_t a_ = (uint32_t)__cvta_generic_to_shared(p); \
    asm volatile("ldmatrix.sync.aligned.m8n8.x4.trans.shared.b16 {%0,%1,%2,%3}, [%4];" \
        : "=r"(f[0]), "=r"(f[1]), "=r"(f[2]), "=r"(f[3]) : "r"(a_)); \
} while (0)

#define MMAH(d, a, b0, b1) \
    asm volatile("mma.sync.aligned.m16n8k16.row.col.f32.f16.f16.f32 " \
        "{%0,%1,%2,%3}, {%4,%5,%6,%7}, {%8,%9}, {%0,%1,%2,%3};" \
        : "+f"(d[0]), "+f"(d[1]), "+f"(d[2]), "+f"(d[3]) \
        : "r"(a[0]), "r"(a[1]), "r"(a[2]), "r"(a[3]), "r"(b0), "r"(b1))

// ================= fp16 tensor-core GEMM, CTA 128x128, warp 32x64 ================
#define SA_STRIDE 40     // 32 + 8 pad (half elems)
#define SB_STRIDE 136    // 128 + 8 pad
#define SA_STAGE  (128*SA_STRIDE)   // 5120
#define SB_STAGE  (32*SB_STRIDE)    // 4352
#define HG_SMEM ((SA_STAGE + SB_STAGE) * 2 * 2)   // 37888 bytes

__device__ __forceinline__ void hg_load_stage(
    const __half* __restrict__ Ag, const __half* __restrict__ Bg,
    __half* sA, __half* sB, int tid, size_t m0, size_t n0, int Kk, int Nn, int k0)
{
    // A: 128 rows x 32 cols = 512 16B-chunks (2/thread)
#pragma unroll
    for (int it = 0; it < 2; it++) {
        int c = it*256 + tid;
        int r = c >> 2, col = (c & 3) << 3;
        cp16(sA + r * SA_STRIDE + col, Ag + (m0 + r) * (size_t)Kk + k0 + col);
    }
    // B: 32 rows x 128 cols = 512 chunks (2/thread)
#pragma unroll
    for (int it = 0; it < 2; it++) {
        int c = it*256 + tid;
        int r = c >> 4, col = (c & 15) << 3;
        cp16(sB + r * SB_STRIDE + col, Bg + (size_t)(k0 + r) * Nn + n0 + col);
    }
    asm volatile("cp.async.commit_group;");
}

__global__ void __launch_bounds__(256)
hgemm_kernel(const __half* __restrict__ Ag, const __half* __restrict__ Bg,
             int Kk, int Nn,
             const float* __restrict__ bias, int relu, const float* __restrict__ resid,
             float* __restrict__ C, __half* __restrict__ Ch)
{
    extern __shared__ __half smem[];
    __half* sA = smem;
    __half* sB = smem + 2*SA_STAGE;

    int tid = threadIdx.x;
    int warp = tid >> 5, lane = tid & 31;
    int wm = warp >> 1, wn = warp & 1;          // 4x2 warps, warp tile 32x64
    size_t m0 = (size_t)blockIdx.y * 128;
    size_t n0 = (size_t)blockIdx.x * 128;

    float acc[2][8][4];
#pragma unroll
    for (int i = 0; i < 2; i++)
#pragma unroll
        for (int j = 0; j < 8; j++)
#pragma unroll
            for (int t = 0; t < 4; t++) acc[i][j][t] = 0.f;

    int nk = Kk >> 5;
    hg_load_stage(Ag, Bg, sA, sB, tid, m0, n0, Kk, Nn, 0);

    for (int kt = 0; kt < nk; kt++) {
        int cur = kt & 1;
        if (kt + 1 < nk) {
            hg_load_stage(Ag, Bg, sA + ((kt+1)&1)*SA_STAGE, sB + ((kt+1)&1)*SB_STAGE,
                          tid, m0, n0, Kk, Nn, (kt+1)*32);
            asm volatile("cp.async.wait_group 1;");
        } else {
            asm volatile("cp.async.wait_group 0;");
        }
        __syncthreads();

        __half* a = sA + cur*SA_STAGE;
        __half* bb = sB + cur*SB_STAGE;

#pragma unroll
        for (int k16 = 0; k16 < 32; k16 += 16) {
            uint32_t af[2][4], bf[4][4];
#pragma unroll
            for (int mi = 0; mi < 2; mi++)
                LDSM4(af[mi], a + (size_t)(wm*32 + mi*16 + (lane & 15)) * SA_STRIDE
                                + k16 + (lane >> 4) * 8);
#pragma unroll
            for (int nb = 0; nb < 4; nb++)
                LDSM4T(bf[nb], bb + (size_t)(k16 + (lane & 15)) * SB_STRIDE
                                  + wn*64 + nb*16 + (lane >> 4) * 8);
#pragma unroll
            for (int mi = 0; mi < 2; mi++)
#pragma unroll
                for (int ni = 0; ni < 8; ni++) {
                    int nb = ni >> 1, sel = (ni & 1) * 2;
                    MMAH(acc[mi][ni], af[mi], bf[nb][sel], bf[nb][sel+1]);
                }
        }
        __syncthreads();
    }

    // epilogue
#pragma unroll
    for (int mi = 0; mi < 2; mi++)
#pragma unroll
        for (int ni = 0; ni < 8; ni++) {
            int col = wn*64 + ni*8 + (lane & 3) * 2;
#pragma unroll
            for (int hh = 0; hh < 2; hh++) {
                int row = wm*32 + mi*16 + (lane >> 2) + hh*8;
                float v0 = acc[mi][ni][hh*2], v1 = acc[mi][ni][hh*2+1];
                size_t o = (m0 + row) * (size_t)Nn + n0 + col;
                if (bias) { v0 += bias[n0+col]; v1 += bias[n0+col+1]; }
                if (resid) { v0 += resid[o]; v1 += resid[o+1]; }
                if (relu) { v0 = fmaxf(v0, 0.f); v1 = fmaxf(v1, 0.f); }
                if (C) { C[o] = v0; C[o+1] = v1; }
                if (Ch) *(uint32_t*)(Ch + o) = packh2(v0, v1);
            }
        }
}

// ---------------- fp32 -> fp16 convert ------------------------------------------
__global__ void __launch_bounds__(256)
cvt_kernel(const float4* __restrict__ in, __half2* __restrict__ out, int nquads)
{
    int i = blockIdx.x * 256 + threadIdx.x;
    if (i >= nquads) return;
    float4 v = in[i];
    out[2*i]   = __floats2half2_rn(v.x, v.y);
    out[2*i+1] = __floats2half2_rn(v.z, v.w);
}

// ================= flash attention (fp16 mma) ====================================
#define AT_STR 136
#define AT_TILE (64*AT_STR)
#define ATTN_SMEM_BYTES (3 * AT_TILE * 2)

__global__ void __launch_bounds__(128)
attn_mma_kernel(const __half* __restrict__ q, const __half* __restrict__ k,
                const __half* __restrict__ v, float* __restrict__ att)
{
    extern __shared__ __half sm[];
    __half* Qs = sm;
    __half* Ks = sm + AT_TILE;
    __half* Vs = sm + 2*AT_TILE;

    int qt = blockIdx.x, seg = blockIdx.y, bh = blockIdx.z;
    int b = bh >> 4, h = bh & 15;
    int tid = threadIdx.x, warp = tid >> 5, lane = tid & 31;
    const float scale = 0.08838834764831845f;
    size_t base = ((size_t)(b*S_ + seg*SEG_) * H_ + h) * DK_;

#pragma unroll
    for (int it = 0; it < 8; it++) {
        int e = it*128 + tid, r = e >> 4, c8 = (e & 15) << 3;
        size_t go = base + (size_t)(qt*64 + r)*2048 + c8;
        *(uint4*)(Qs + r*AT_STR + c8) = *(const uint4*)(q + go);
    }

    float o[16][4];
#pragma unroll
    for (int t = 0; t < 16; t++)
#pragma unroll
        for (int j = 0; j < 4; j++) o[t][j] = 0.f;
    float m0 = -1e30f, m1 = -1e30f, l0 = 0.f, l1 = 0.f;
    int r0g = qt*64 + warp*16 + (lane >> 2);
    int r1g = r0g + 8;

    for (int kt = 0; kt <= qt; kt++) {
        __syncthreads();
#pragma unroll
        for (int it = 0; it < 8; it++) {
            int e = it*128 + tid, r = e >> 4, c8 = (e & 15) << 3;
            size_t go = base + (size_t)(kt*64 + r)*2048 + c8;
            *(uint4*)(Ks + r*AT_STR + c8) = *(const uint4*)(k + go);
            *(uint4*)(Vs + r*AT_STR + c8) = *(const uint4*)(v + go);
        }
        __syncthreads();

        float s[8][4];
#pragma unroll
        for (int t = 0; t < 8; t++)
#pragma unroll
            for (int j = 0; j < 4; j++) s[t][j] = 0.f;

#pragma unroll
        for (int kk = 0; kk < 8; kk++) {
            uint32_t qa[4];
            LDSM4(qa, Qs + (size_t)(warp*16 + (lane & 15))*AT_STR + kk*16 + (lane >> 4)*8);
#pragma unroll
            for (int ng = 0; ng < 4; ng++) {
                uint32_t kf[4];
                LDSM4(kf, Ks + (size_t)(ng*16 + (lane & 15))*AT_STR + kk*16 + (lane >> 4)*8);
                MMAH(s[2*ng],   qa, kf[0], kf[2]);
                MMAH(s[2*ng+1], qa, kf[1], kf[3]);
            }
        }

        float mx0 = -1e30f, mx1 = -1e30f;
#pragma unroll
        for (int t = 0; t < 8; t++) {
            int colb = kt*64 + t*8 + (lane & 3)*2;
            float a0 = s[t][0]*scale, a1 = s[t][1]*scale;
            float a2 = s[t][2]*scale, a3 = s[t][3]*scale;
            if (kt == qt) {
                if (colb     > r0g) a0 = -1e30f;
                if (colb + 1 > r0g) a1 = -1e30f;
                if (colb     > r1g) a2 = -1e30f;
                if (colb + 1 > r1g) a3 = -1e30f;
            }
            s[t][0] = a0; s[t][1] = a1; s[t][2] = a2; s[t][3] = a3;
            mx0 = fmaxf(mx0, fmaxf(a0, a1));
            mx1 = fmaxf(mx1, fmaxf(a2, a3));
        }
        mx0 = fmaxf(mx0, __shfl_xor_sync(0xffffffffu, mx0, 1));
        mx0 = fmaxf(mx0, __shfl_xor_sync(0xffffffffu, mx0, 2));
        mx1 = fmaxf(mx1, __shfl_xor_sync(0xffffffffu, mx1, 1));
        mx1 = fmaxf(mx1, __shfl_xor_sync(0xffffffffu, mx1, 2));
        float m0n = fmaxf(m0, mx0), m1n = fmaxf(m1, mx1);
        float rc0 = __expf(m0 - m0n), rc1 = __expf(m1 - m1n);
        float sum0 = 0.f, sum1 = 0.f;
#pragma unroll
        for (int t = 0; t < 8; t++) {
            s[t][0] = __expf(s[t][0] - m0n); sum0 += s[t][0];
            s[t][1] = __expf(s[t][1] - m0n); sum0 += s[t][1];
            s[t][2] = __expf(s[t][2] - m1n); sum1 += s[t][2];
            s[t][3] = __expf(s[t][3] - m1n); sum1 += s[t][3];
        }
        sum0 += __shfl_xor_sync(0xffffffffu, sum0, 1);
        sum0 += __shfl_xor_sync(0xffffffffu, sum0, 2);
        sum1 += __shfl_xor_sync(0xffffffffu, sum1, 1);
        sum1 += __shfl_xor_sync(0xffffffffu, sum1, 2);
        l0 = l0*rc0 + sum0;  l1 = l1*rc1 + sum1;
        m0 = m0n;  m1 = m1n;
#pragma unroll
        for (int t = 0; t < 16; t++) {
            o[t][0] *= rc0; o[t][1] *= rc0; o[t][2] *= rc1; o[t][3] *= rc1;
        }

        // O += P V (single pass)
#pragma unroll
        for (int kk = 0; kk < 4; kk++) {
            uint32_t ah[4];
            ah[0] = packh2(s[2*kk][0],   s[2*kk][1]);
            ah[1] = packh2(s[2*kk][2],   s[2*kk][3]);
            ah[2] = packh2(s[2*kk+1][0], s[2*kk+1][1]);
            ah[3] = packh2(s[2*kk+1][2], s[2*kk+1][3]);
#pragma unroll
            for (int dg = 0; dg < 8; dg++) {
                uint32_t vf[4];
                LDSM4T(vf, Vs + (size_t)(kk*16 + (lane & 15))*AT_STR + dg*16 + (lane >> 4)*8);
                MMAH(o[2*dg],   ah, vf[0], vf[1]);
                MMAH(o[2*dg+1], ah, vf[2], vf[3]);
            }
        }
    }

    float inv0 = 1.f / l0, inv1 = 1.f / l1;
#pragma unroll
    for (int t = 0; t < 16; t++) {
        size_t ro = base + (size_t)(qt*64 + warp*16 + (lane >> 2))*2048 + t*8 + (lane & 3)*2;
        float2 w0; w0.x = o[t][0]*inv0; w0.y = o[t][1]*inv0;
        float2 w1; w1.x = o[t][2]*inv1; w1.y = o[t][3]*inv1;
        *(float2*)(att + ro)          = w0;
        *(float2*)(att + ro + 8*2048) = w1;
    }
}

// ================= memory update: U = sig(K)^T V (fp16 mma) ======================
#define MU_KSTR 72
#define MU_KTILE (128*MU_KSTR)
#define MU_VSTR 136
#define MU_VTILE (64*MU_VSTR)
#define MEMUPD_SMEM ((MU_KTILE + MU_VTILE) * 2)

__global__ void __launch_bounds__(256)
memupd_mma_kernel(const __half* __restrict__ k, const __half* __restrict__ v,
                  float* __restrict__ U, float* __restrict__ zU)
{
    extern __shared__ __half sm[];
    __half* sK = sm;                    // [dk 128][s 64] transposed
    __half* sV = sm + MU_KTILE;         // [s 64][dv 128]
    __shared__ float zsm[128];

    int seg = blockIdx.x & 7, bhx = blockIdx.x >> 3;
    int b = bhx >> 4, h = bhx & 15;
    int tid = threadIdx.x, warp = tid >> 5, lane = tid & 31;
    int wm = warp >> 1, wn = warp & 1;
    size_t base = ((size_t)(b*S_ + seg*SEG_) * H_ + h) * DK_;

    if (tid < 128) zsm[tid] = 0.f;

    float acc[2][8][4];
#pragma unroll
    for (int i = 0; i < 2; i++)
#pragma unroll
        for (int j = 0; j < 8; j++)
#pragma unroll
            for (int t = 0; t < 4; t++) acc[i][j][t] = 0.f;

    for (int st = 0; st < 8; st++) {
        int s0 = st * 64;
        // build sig(K)^T tile
#pragma unroll
        for (int it = 0; it < 16; it++) {
            int e = it*256 + tid, s = e >> 6, c2 = e & 63;
            size_t go = base + (size_t)(s0 + s)*2048 + 2*c2;
            __half2 h2 = *(const __half2*)(k + go);
            float f0 = elu1(__low2float(h2));
            float f1 = elu1(__high2float(h2));
            sK[(2*c2)  *MU_KSTR + s] = __float2half_rn(f0);
            sK[(2*c2+1)*MU_KSTR + s] = __float2half_rn(f1);
        }
#pragma unroll
        for (int it = 0; it < 4; it++) {
            int e = it*256 + tid, r = e >> 4, c8 = (e & 15) << 3;
            size_t go = base + (size_t)(s0 + r)*2048 + c8;
            *(uint4*)(sV + r*MU_VSTR + c8) = *(const uint4*)(v + go);
        }
        __syncthreads();

        if (tid < 128) {
            float zz = 0.f;
#pragma unroll 4
            for (int s = 0; s < 64; s++) zz += __half2float(sK[tid*MU_KSTR + s]);
            zsm[tid] += zz;
        }

#pragma unroll
        for (int kk = 0; kk < 4; kk++) {
            uint32_t a[2][4];
#pragma unroll
            for (int mi = 0; mi < 2; mi++)
                LDSM4(a[mi], sK + (size_t)(wm*32 + mi*16 + (lane & 15))*MU_KSTR + kk*16 + (lane >> 4)*8);
#pragma unroll
            for (int ng = 0; ng < 4; ng++) {
                uint32_t bb[4];
                LDSM4T(bb, sV + (size_t)(kk*16 + (lane & 15))*MU_VSTR + wn*64 + ng*16 + (lane >> 4)*8);
#pragma unroll
                for (int mi = 0; mi < 2; mi++) {
                    MMAH(acc[mi][2*ng],   a[mi], bb[0], bb[1]);
                    MMAH(acc[mi][2*ng+1], a[mi], bb[2], bb[3]);
                }
            }
        }
        __syncthreads();
    }

    size_t ob = (size_t)blockIdx.x * (DK_*DV_);
#pragma unroll
    for (int mi = 0; mi < 2; mi++)
#pragma unroll
        for (int ni = 0; ni < 8; ni++) {
            int col = wn*64 + ni*8 + (lane & 3)*2;
#pragma unroll
            for (int hh = 0; hh < 2; hh++) {
                int row = wm*32 + mi*16 + (lane >> 2) + hh*8;
                float2 w; w.x = acc[mi][ni][hh*2]; w.y = acc[mi][ni][hh*2+1];
                *(float2*)(U + ob + (size_t)row*128 + col) = w;
            }
        }
    if (tid < 128) zU[(size_t)blockIdx.x*128 + tid] = zsm[tid];
}

// ---------------- exclusive prefix over segments --------------------------------
__global__ void __launch_bounds__(256)
prefix_kernel(const float* __restrict__ U, const float* __restrict__ zU,
              float* __restrict__ Mem, float* __restrict__ Z)
{
    int bh = blockIdx.x, tid = threadIdx.x;
    for (int idx = tid; idx < DK_*DV_; idx += 256) {
        float run = 0.f;
#pragma unroll
        for (int sg = 0; sg < NSEG_; sg++) {
            size_t o = ((size_t)(bh*NSEG_ + sg)) * (DK_*DV_) + idx;
            Mem[o] = run;
            run += U[o];
        }
    }
    if (tid < 128) {
        float run = 1.f / 128.f;
#pragma unroll
        for (int sg = 0; sg < NSEG_; sg++) {
            size_t o = (size_t)(bh*NSEG_ + sg) * 128 + tid;
            Z[o] = run;
            run += zU[o];
        }
    }
}

// ================= retrieval + gate combine (fp16 mma) ===========================
#define RT_STR 136
#define RT_TILE (128*RT_STR)
#define RETR_SMEM (2 * RT_TILE * 2)

__global__ void __launch_bounds__(256)
retrieve_mma_kernel(const __half* __restrict__ q, const float* __restrict__ Mem,
                    const float* __restrict__ Z, const float* __restrict__ betas,
                    const float* __restrict__ attdot, __half* __restrict__ at)
{
    extern __shared__ __half sm[];
    __half* Mh = sm;                 // [dk 128][dv 128]
    __half* Sh = sm + RT_TILE;       // sigma(Q) [s 128][dk 128]
    __shared__ float den[128], zz[128], gate[128];

    int seg = blockIdx.x & 7, bhx = blockIdx.x >> 3;
    int b = bhx >> 4, h = bhx & 15;
    int tid = threadIdx.x, warp = tid >> 5, lane = tid & 31;
    size_t base = ((size_t)(b*S_ + seg*SEG_) * H_ + h) * DK_;
    size_t mb = (size_t)blockIdx.x * 16384;

    if (tid < 128) {
        gate[tid] = 1.f / (1.f + __expf(-betas[h*128 + tid]));
        zz[tid]   = Z[(size_t)blockIdx.x*128 + tid];
    }
#pragma unroll
    for (int it = 0; it < 16; it++) {
        int e = it*256 + tid, r = e >> 5, c4 = (e & 31) << 2;
        float4 v = *(const float4*)(Mem + mb + (size_t)r*128 + c4);
        *(__half2*)(Mh + r*RT_STR + c4)     = __floats2half2_rn(v.x, v.y);
        *(__half2*)(Mh + r*RT_STR + c4 + 2) = __floats2half2_rn(v.z, v.w);
    }
    __syncthreads();

    for (int ch = 0; ch < 4; ch++) {
        int s0 = ch * 128;
#pragma unroll
        for (int it = 0; it < 32; it++) {
            int e = it*256 + tid, s = e >> 6, c2 = e & 63;
            size_t go = base + (size_t)(s0 + s)*2048 + 2*c2;
            __half2 h2 = *(const __half2*)(q + go);
            float f0 = elu1(__low2float(h2));
            float f1 = elu1(__high2float(h2));
            *(__half2*)(Sh + s*RT_STR + 2*c2) = __floats2half2_rn(f0, f1);
        }
        __syncthreads();
        if (tid < 128) {
            float d = 0.f;
#pragma unroll 4
            for (int dk = 0; dk < 128; dk++)
                d += __half2float(Sh[tid*RT_STR + dk]) * zz[dk];
            den[tid] = d;
        }
        __syncthreads();

        float o[16][4];
#pragma unroll
        for (int t = 0; t < 16; t++)
#pragma unroll
            for (int j = 0; j < 4; j++) o[t][j] = 0.f;

#pragma unroll
        for (int kk = 0; kk < 8; kk++) {
            uint32_t qa[4];
            LDSM4(qa, Sh + (size_t)(warp*16 + (lane & 15))*RT_STR + kk*16 + (lane >> 4)*8);
#pragma unroll
            for (int ng = 0; ng < 8; ng++) {
                uint32_t mh4[4];
                LDSM4T(mh4, Mh + (size_t)(kk*16 + (lane & 15))*RT_STR + ng*16 + (lane >> 4)*8);
                MMAH(o[2*ng],   qa, mh4[0], mh4[1]);
                MMAH(o[2*ng+1], qa, mh4[2], mh4[3]);
            }
        }

        float inv0 = 1.f / den[warp*16 + (lane >> 2)];
        float inv1 = 1.f / den[warp*16 + (lane >> 2) + 8];
#pragma unroll
        for (int t = 0; t < 16; t++) {
            int col = t*8 + (lane & 3)*2;
            float g0 = gate[col], g1 = gate[col+1];
            size_t ro = base + (size_t)(s0 + warp*16 + (lane >> 2))*2048 + col;
            float2 d0 = *(const float2*)(attdot + ro);
            float2 d1 = *(const float2*)(attdot + ro + 8*2048);
            float v0 = g0*(o[t][0]*inv0) + (1.f - g0)*d0.x;
            float v1 = g1*(o[t][1]*inv0) + (1.f - g1)*d0.y;
            float v2 = g0*(o[t][2]*inv1) + (1.f - g0)*d1.x;
            float v3 = g1*(o[t][3]*inv1) + (1.f - g1)*d1.y;
            *(uint32_t*)(at + ro)          = packh2(v0, v1);
            *(uint32_t*)(at + ro + 8*2048) = packh2(v2, v3);
        }
        __syncthreads();
    }
}

// ---------------- LayerNorm -----------------------------------------------------
__global__ void __launch_bounds__(256)
ln_kernel(const float* __restrict__ y, const float* __restrict__ gg,
          const float* __restrict__ bb, float* __restrict__ out)
{
    size_t row = blockIdx.x;
    const float* p = y + row * D_;
    int tid = threadIdx.x;
    float4 v0 = *(const float4*)(p + tid*8);
    float4 v1 = *(const float4*)(p + tid*8 + 4);
    float s  = v0.x+v0.y+v0.z+v0.w + v1.x+v1.y+v1.z+v1.w;
    float s2 = v0.x*v0.x+v0.y*v0.y+v0.z*v0.z+v0.w*v0.w
             + v1.x*v1.x+v1.y*v1.y+v1.z*v1.z+v1.w*v1.w;
#pragma unroll
    for (int o = 16; o >= 1; o >>= 1) {
        s  += __shfl_xor_sync(0xffffffffu, s, o);
        s2 += __shfl_xor_sync(0xffffffffu, s2, o);
    }
    __shared__ float red[16];
    __shared__ float stat[2];
    int warp = tid >> 5, lane = tid & 31;
    if (lane == 0) { red[warp] = s; red[warp + 8] = s2; }
    __syncthreads();
    if (tid == 0) {
        float S = 0.f, S2 = 0.f;
#pragma unroll
        for (int w = 0; w < 8; w++) { S += red[w]; S2 += red[w + 8]; }
        float mean = S / (float)D_;
        float var  = S2 / (float)D_ - mean*mean;
        stat[0] = mean;
        stat[1] = rsqrtf(var + 1e-5f);
    }
    __syncthreads();
    float mean = stat[0], inv = stat[1];
    float4 g0 = *(const float4*)(gg + tid*8), g1 = *(const float4*)(gg + tid*8 + 4);
    float4 b0 = *(const float4*)(bb + tid*8), b1 = *(const float4*)(bb + tid*8 + 4);
    float4 o0, o1;
    o0.x = (v0.x-mean)*inv*g0.x + b0.x; o0.y = (v0.y-mean)*inv*g0.y + b0.y;
    o0.z = (v0.z-mean)*inv*g0.z + b0.z; o0.w = (v0.w-mean)*inv*g0.w + b0.w;
    o1.x = (v1.x-mean)*inv*g1.x + b1.x; o1.y = (v1.y-mean)*inv*g1.y + b1.y;
    o1.z = (v1.z-mean)*inv*g1.z + b1.z; o1.w = (v1.w-mean)*inv*g1.w + b1.w;
    *(float4*)(out + row*D_ + tid*8)     = o0;
    *(float4*)(out + row*D_ + tid*8 + 4) = o1;
}

// ---------------- launch --------------------------------------------------------
static inline void cvt_launch(const float* src, __half* dst, size_t nelems)
{
    int nq = (int)(nelems / 4);
    cvt_kernel<<<(nq + 255)/256, 256>>>((const float4*)src, (__half2*)dst, nq);
}

extern "C" void kernel_launch(void* const* d_in, const int* in_sizes, int n_in,
                              void* d_out, int out_size)
{
    const float* x     = (const float*)d_in[0];
    const float* Wq    = (const float*)d_in[1];
    const float* Wk    = (const float*)d_in[2];
    const float* Wv    = (const float*)d_in[3];
    const float* Wo    = (const float*)d_in[4];
    const float* betas = (const float*)d_in[5];
    const float* W1    = (const float*)d_in[6];
    const float* b1    = (const float*)d_in[7];
    const float* W2    = (const float*)d_in[8];
    const float* b2    = (const float*)d_in[9];
    const float* ln_g  = (const float*)d_in[10];
    const float* ln_b  = (const float*)d_in[11];
    float* out = (float*)d_out;

    float *att_, *y_, *U_, *zU_, *mem_, *z_;
    cudaGetSymbolAddress((void**)&att_, g_att);
    cudaGetSymbolAddress((void**)&y_,   g_y);
    cudaGetSymbolAddress((void**)&U_,   g_U);
    cudaGetSymbolAddress((void**)&zU_,  g_zU);
    cudaGetSymbolAddress((void**)&mem_, g_mem);
    cudaGetSymbolAddress((void**)&z_,   g_z);

    __half *xh,*wq,*wk,*wv,*wo,*w1,*w2,*qh,*kh,*vh,*at,*ao,*hh;
    cudaGetSymbolAddress((void**)&xh, g_x);
    cudaGetSymbolAddress((void**)&wq, g_wq);
    cudaGetSymbolAddress((void**)&wk, g_wk);
    cudaGetSymbolAddress((void**)&wv, g_wv);
    cudaGetSymbolAddress((void**)&wo, g_wo);
    cudaGetSymbolAddress((void**)&w1, g_w1);
    cudaGetSymbolAddress((void**)&w2, g_w2);
    cudaGetSymbolAddress((void**)&qh, g_q);
    cudaGetSymbolAddress((void**)&kh, g_k);
    cudaGetSymbolAddress((void**)&vh, g_v);
    cudaGetSymbolAddress((void**)&at, g_at);
    cudaGetSymbolAddress((void**)&ao, g_ao);
    cudaGetSymbolAddress((void**)&hh, g_hh);

    cudaFuncSetAttribute(hgemm_kernel,
        cudaFuncAttributeMaxDynamicSharedMemorySize, HG_SMEM);
    cudaFuncSetAttribute(attn_mma_kernel,
        cudaFuncAttributeMaxDynamicSharedMemorySize, ATTN_SMEM_BYTES);
    cudaFuncSetAttribute(memupd_mma_kernel,
        cudaFuncAttributeMaxDynamicSharedMemorySize, MEMUPD_SMEM);
    cudaFuncSetAttribute(retrieve_mma_kernel,
        cudaFuncAttributeMaxDynamicSharedMemorySize, RETR_SMEM);

    // fp32 -> fp16 converts
    cvt_launch(x,  xh, (size_t)M_ * D_);
    cvt_launch(Wq, wq, (size_t)D_ * D_);
    cvt_launch(Wk, wk, (size_t)D_ * D_);
    cvt_launch(Wv, wv, (size_t)D_ * D_);
    cvt_launch(Wo, wo, (size_t)D_ * D_);
    cvt_launch(W1, w1, (size_t)D_ * DH_);
    cvt_launch(W2, w2, (size_t)DH_ * D_);

    dim3 gProj(D_/128, M_/128);          // (16, 64)
    dim3 gMlp1(DH_/128, M_/128);         // (64, 64)

    // QKV projections -> fp16 directly
    hgemm_kernel<<<gProj, 256, HG_SMEM>>>(xh, wq, D_, D_, nullptr, 0, nullptr, nullptr, qh);
    hgemm_kernel<<<gProj, 256, HG_SMEM>>>(xh, wk, D_, D_, nullptr, 0, nullptr, nullptr, kh);
    hgemm_kernel<<<gProj, 256, HG_SMEM>>>(xh, wv, D_, D_, nullptr, 0, nullptr, nullptr, vh);

    // attention paths (fp16 tensor cores)
    attn_mma_kernel<<<dim3(8, 8, 32), 128, ATTN_SMEM_BYTES>>>(qh, kh, vh, att_);
    memupd_mma_kernel<<<256, 256, MEMUPD_SMEM>>>(kh, vh, U_, zU_);
    prefix_kernel<<<32, 256>>>(U_, zU_, mem_, z_);
    retrieve_mma_kernel<<<256, 256, RETR_SMEM>>>(qh, mem_, z_, betas, att_, at);

    // Wo / MLP chain
    hgemm_kernel<<<gProj, 256, HG_SMEM>>>(at, wo, D_, D_, nullptr, 0, nullptr, nullptr, ao);
    hgemm_kernel<<<gMlp1, 256, HG_SMEM>>>(ao, w1, D_, DH_, b1, 1, nullptr, nullptr, hh);
    hgemm_kernel<<<gProj, 256, HG_SMEM>>>(hh, w2, DH_, D_, b2, 0, x, y_, nullptr);
    ln_kernel<<<M_, 256>>>(y_, ln_g, ln_b, out);
}